// round 12
// baseline (speedup 1.0000x reference)
#include <cuda_runtime.h>
#include <cstdint>

// Shapes fixed for this benchmark
constexpr int B_ = 8, NA = 4096, NB = 4096, D_ = 64;
constexpr int GC = 8;                 // 16-wide cells per axis -> 8^3 = 512 cells
constexpr int NCELL = GC * GC * GC;   // 512
constexpr int NSC = 64;               // 32-wide supercells -> 4^3
constexpr int CAP = 3072;             // SMEM candidate capacity (avg region ~344)
constexpr int TM = 128;               // k_main threads (4 warps)
constexpr int TB = 512;               // k_bin threads

// Scratch (device globals: no allocation allowed)
__device__ int g_bstart[B_][NCELL + 1];
__device__ int g_astart[B_][NSC + 1];
__device__ uint32_t g_bpack[B_][NB];  // cell-sorted packed (x|y<<8|z<<16), coords >>4
__device__ int      g_bidx[B_][NB];   // original b index (gather + tie-break)
__device__ uint32_t g_apack[B_][NA];
__device__ int      g_aidx[B_][NA];   // original a row

// ---------------------------------------------------------------------------
// Binning: grid (B_, 2). y=0: b-points into 512 cells; y=1: a-points into 64
// supercells. Histogram via SMEM atomics, warp-shuffle scans, SMEM-cursor scatter.
// ---------------------------------------------------------------------------
__global__ __launch_bounds__(TB) void k_bin(
    const int* __restrict__ ac, const int* __restrict__ bc)
{
    const int b = blockIdx.x, t = threadIdx.x, lane = t & 31, wid = t >> 5;

    if (blockIdx.y == 0) {
        // ---- b role: 512 cells ----
        __shared__ int h[NCELL];
        __shared__ int wsum[16];
        h[t] = 0;
        __syncthreads();

        uint32_t pk[8]; int cl[8];
        const int* base = bc + (size_t)b * NB * 3;
        #pragma unroll
        for (int i = 0; i < 8; i++) {
            const int m = t + i * TB;
            const int* c = base + (size_t)m * 3;
            uint32_t x = ((uint32_t)c[0]) >> 4, y = ((uint32_t)c[1]) >> 4, z = ((uint32_t)c[2]) >> 4;
            pk[i] = x | (y << 8) | (z << 16);
            cl[i] = (int)(x >> 4) + GC * (int)(y >> 4) + GC * GC * (int)(z >> 4);
            atomicAdd(&h[cl[i]], 1);
        }
        __syncthreads();

        const int v = h[t];
        int incl = v;
        #pragma unroll
        for (int d = 1; d < 32; d <<= 1) {
            int u = __shfl_up_sync(~0u, incl, d);
            if (lane >= d) incl += u;
        }
        if (lane == 31) wsum[wid] = incl;
        __syncthreads();
        if (wid == 0) {
            int s = (lane < 16) ? wsum[lane] : 0;
            #pragma unroll
            for (int d = 1; d < 16; d <<= 1) {
                int u = __shfl_up_sync(~0u, s, d);
                if (lane >= d) s += u;
            }
            if (lane < 16) wsum[lane] = s;
        }
        __syncthreads();
        const int inclT = incl + (wid > 0 ? wsum[wid - 1] : 0);
        g_bstart[b][t + 1] = inclT;
        if (t == 0) g_bstart[b][0] = 0;
        h[t] = inclT - v;          // exclusive -> cursor (own slot only)
        __syncthreads();

        uint32_t* bp = g_bpack[b];
        int*      bi = g_bidx[b];
        #pragma unroll
        for (int i = 0; i < 8; i++) {
            const int m = t + i * TB;
            const int pos = atomicAdd(&h[cl[i]], 1);
            bp[pos] = pk[i];
            bi[pos] = m;
        }
    } else {
        // ---- a role: 64 supercells ----
        __shared__ int h[NSC];
        __shared__ int wsum[2];
        if (t < NSC) h[t] = 0;
        __syncthreads();

        uint32_t pk[8]; int cl[8];
        const int* base = ac + (size_t)b * NA * 3;
        #pragma unroll
        for (int i = 0; i < 8; i++) {
            const int m = t + i * TB;
            const int* c = base + (size_t)m * 3;
            uint32_t x = ((uint32_t)c[0]) >> 4, y = ((uint32_t)c[1]) >> 4, z = ((uint32_t)c[2]) >> 4;
            pk[i] = x | (y << 8) | (z << 16);
            cl[i] = (int)(x >> 5) + 4 * (int)(y >> 5) + 16 * (int)(z >> 5);
            atomicAdd(&h[cl[i]], 1);
        }
        __syncthreads();

        int v = 0, incl = 0;
        if (t < NSC) {
            v = h[t];
            incl = v;
            #pragma unroll
            for (int d = 1; d < 32; d <<= 1) {
                int u = __shfl_up_sync(~0u, incl, d);
                if (lane >= d) incl += u;
            }
            if (lane == 31) wsum[wid] = incl;
        }
        __syncthreads();
        if (t < NSC) {
            const int inclT = incl + (wid == 1 ? wsum[0] : 0);
            g_astart[b][t + 1] = inclT;
            if (t == 0) g_astart[b][0] = 0;
            h[t] = inclT - v;
        }
        __syncthreads();

        uint32_t* apg = g_apack[b];
        int*      aig = g_aidx[b];
        #pragma unroll
        for (int i = 0; i < 8; i++) {
            const int m = t + i * TB;
            const int pos = atomicAdd(&h[cl[i]], 1);
            apg[pos] = pk[i];
            aig[pos] = m;
        }
    }
}

__device__ __forceinline__ void insert3(uint32_t key, uint32_t& b0, uint32_t& b1, uint32_t& b2) {
    uint32_t t1 = min(b1, max(b0, key));
    uint32_t t2 = min(b2, max(b1, key));
    b0 = min(b0, key);
    b1 = t1;
    b2 = t2;
}

// ---------------------------------------------------------------------------
// Main: grid (NSC, B_), block 128. Stage candidates once; then each warp
// autonomously processes whole 32-point a-sets (scan + weights + epilogue),
// no cross-warp synchronization after staging.
// ---------------------------------------------------------------------------
__global__ __launch_bounds__(TM) void k_main(
    const float* __restrict__ a_feats, const float* __restrict__ b_feats,
    float* __restrict__ out)
{
    __shared__ uint4  sm_c4[CAP / 2];     // interleaved (pack,idx) pairs, 2 cand/uint4
    __shared__ int    sm_rs[16];
    __shared__ int    sm_ro[17];
    __shared__ int4   sm_ri[4][32];       // per-warp: {i0,i1,i2,orow} (16B-aligned)
    __shared__ float4 sm_rw[4][32];       // per-warp: {w0,w1,w2,pad}  (16B-aligned)

    const int b = blockIdx.y, scid = blockIdx.x;
    const int tid = threadIdx.x, lane = tid & 31, w = tid >> 5;

    const int astart = g_astart[b][scid], aend = g_astart[b][scid + 1];
    const int acount = aend - astart;
    if (acount == 0) return;

    // Candidate region: 4x4x4 cells around the supercell (clipped)
    const int sx = scid & 3, sy = (scid >> 2) & 3, sz = scid >> 4;
    const int x0 = max(0, 2 * sx - 1), x1 = min(GC - 1, 2 * sx + 2);
    const int y0 = max(0, 2 * sy - 1), y1 = min(GC - 1, 2 * sy + 2);
    const int z0 = max(0, 2 * sz - 1), z1 = min(GC - 1, 2 * sz + 2);
    const int ny = y1 - y0 + 1, nz = z1 - z0 + 1, nrun = ny * nz;

    const uint32_t* __restrict__ bpack = g_bpack[b];
    const int*      __restrict__ bidx  = g_bidx[b];

    // Warp-0 region setup with shfl prefix sum
    if (w == 0) {
        int s = 0, len = 0;
        if (lane < nrun) {
            const int cy = y0 + lane % ny, cz = z0 + lane / ny;
            const int c0 = x0 + GC * cy + GC * GC * cz;
            s = g_bstart[b][c0];
            len = g_bstart[b][c0 + (x1 - x0) + 1] - s;
        }
        int off = len;
        #pragma unroll
        for (int d = 1; d < 32; d <<= 1) {
            int u = __shfl_up_sync(~0u, off, d);
            if (lane >= d) off += u;
        }
        if (lane < nrun) { sm_rs[lane] = s; sm_ro[lane] = off - len; }
        if (lane == 31) sm_ro[nrun] = off;
    }
    __syncthreads();

    const int total = sm_ro[nrun];
    const int insm  = min(total, CAP);
    uint2* sm_c = (uint2*)sm_c4;
    for (int r = 0; r < nrun; r++) {
        const int o0 = sm_ro[r], o1 = min(sm_ro[r + 1], insm);
        const int gsrc = sm_rs[r] - o0;
        for (int i = o0 + tid; i < o1; i += TM)
            sm_c[i] = make_uint2(bpack[gsrc + i], (uint32_t)bidx[gsrc + i]);
    }
    const int npair = (insm + 1) >> 1;
    for (int i = insm + tid; i < npair * 2; i += TM)
        sm_c[i] = make_uint2(0xFF000000u, 0u);   // key > any real key; triggers fallback if picked
    __syncthreads();

    const int nsets = (acount + 31) >> 5;
    const float* bf = b_feats + (size_t)b * NB * D_;

    for (int aset = w; aset < nsets; aset += 4) {
        const int ap = astart + aset * 32 + lane;
        const bool valid = ap < aend;
        const uint32_t pa = valid ? g_apack[b][ap] : 0u;

        // Dual accumulator triples break the serial min/max chain
        uint32_t a0 = ~0u, a1 = ~0u, a2 = ~0u;
        uint32_t c0 = ~0u, c1 = ~0u, c2 = ~0u;

        #pragma unroll 2
        for (int j = 0; j < npair; j++) {
            const uint4 cd = sm_c4[j];           // broadcast: 2 candidates
            uint32_t v, d2;
            v = __vabsdiffu4(pa, cd.x); d2 = __dp4a(v, v, 0u);
            insert3(d2 * 4096u + cd.y, a0, a1, a2);
            v = __vabsdiffu4(pa, cd.z); d2 = __dp4a(v, v, 0u);
            insert3(d2 * 4096u + cd.w, c0, c1, c2);
        }
        insert3(c0, a0, a1, a2);
        insert3(c1, a0, a1, a2);
        insert3(c2, a0, a1, a2);

        if (total > insm) {  // overflow remainder from global (broadcast), rare
            for (int r = 0; r < nrun; r++) {
                const int o0 = sm_ro[r], o1 = sm_ro[r + 1];
                const int gsrc = sm_rs[r] - o0;
                for (int i = max(o0, insm); i < o1; i++) {
                    const uint32_t cc = bpack[gsrc + i];
                    const uint32_t mm = (uint32_t)bidx[gsrc + i];
                    const uint32_t vv = __vabsdiffu4(pa, cc);
                    const uint32_t d2 = __dp4a(vv, vv, 0u);
                    insert3(d2 * 4096u + mm, a0, a1, a2);
                }
            }
        }

        // Exactness: region covers ball(a,16). If 3rd-best d2 >= 256, exact full scan.
        if (valid && (a2 >> 12) >= 256u) {
            a0 = a1 = a2 = ~0u;
            for (int m = 0; m < NB; m++) {
                const uint32_t vv = __vabsdiffu4(pa, bpack[m]);
                const uint32_t d2 = __dp4a(vv, vv, 0u);
                insert3(d2 * 4096u + (uint32_t)bidx[m], a0, a1, a2);
            }
        }

        {
            const uint32_t keys[3] = { a0, a1, a2 };
            int   ii[3]; float ww[3];
            #pragma unroll
            for (int k = 0; k < 3; k++) {
                const uint32_t d2 = keys[k] >> 12;
                ii[k] = (int)(keys[k] & 0xFFFu);
                const float dist = sqrtf((float)d2) * (1.0f / 128.0f);
                ww[k] = fmaxf(0.5f - dist, 0.0f);
            }
            sm_ri[w][lane] = make_int4(ii[0], ii[1], ii[2], valid ? g_aidx[b][ap] : 0);
            sm_rw[w][lane] = make_float4(ww[0], ww[1], ww[2], 0.0f);
        }
        __syncwarp();

        // Warp-cooperative epilogue: one row at a time, 32 float4 columns
        const int nval = min(32, acount - aset * 32);
        for (int r = 0; r < nval; r++) {
            const int4   ri = sm_ri[w][r];       // LDS.128 broadcast
            const float4 rw = sm_rw[w][r];
            const int orow = ri.w;
            float4 val;
            if (lane < 16) {
                val = ((const float4*)(a_feats + ((size_t)b * NA + orow) * D_))[lane];
            } else {
                const int cc = lane - 16;
                const float4 f0 = ((const float4*)(bf + (size_t)ri.x * D_))[cc];
                const float4 f1 = ((const float4*)(bf + (size_t)ri.y * D_))[cc];
                const float4 f2 = ((const float4*)(bf + (size_t)ri.z * D_))[cc];
                val.x = rw.x * f0.x + rw.y * f1.x + rw.z * f2.x;
                val.y = rw.x * f0.y + rw.y * f1.y + rw.z * f2.y;
                val.z = rw.x * f0.z + rw.y * f1.z + rw.z * f2.z;
                val.w = rw.x * f0.w + rw.y * f1.w + rw.z * f2.w;
            }
            ((float4*)(out + ((size_t)b * NA + orow) * 2 * D_))[lane] = val;
        }
        __syncwarp();   // protect sm_ri/sm_rw before next a-set
    }
}

extern "C" void kernel_launch(void* const* d_in, const int* in_sizes, int n_in,
                              void* d_out, int out_size)
{
    const float* a_feats  = (const float*)d_in[0];
    const float* b_feats  = (const float*)d_in[1];
    const int*   a_coords = (const int*)d_in[2];
    const int*   b_coords = (const int*)d_in[3];
    float*       out      = (float*)d_out;

    dim3 gbin(B_, 2);
    k_bin<<<gbin, TB>>>(a_coords, b_coords);
    dim3 grid(NSC, B_);
    k_main<<<grid, TM>>>(a_feats, b_feats, out);
}

// round 13
// speedup vs baseline: 1.4012x; 1.4012x over previous
#include <cuda_runtime.h>
#include <cstdint>

// Shapes fixed for this benchmark
constexpr int B_ = 8, NA = 4096, NB = 4096, D_ = 64;
constexpr int GC = 8;                 // 16-wide cells per axis -> 8^3 = 512 cells
constexpr int NCELL = GC * GC * GC;   // 512
constexpr int NSC = 64;               // 32-wide supercells -> 4^3
constexpr int TM = 256;               // k_main threads (8 warps)
constexpr int TB = 512;               // k_bin threads
constexpr int ZS = 4;                 // a-set splits per supercell

// Scratch (device globals: no allocation allowed)
__device__ int   g_bstart[B_][NCELL + 1];
__device__ int   g_astart[B_][NSC + 1];
__device__ uint2 g_bcand[B_][NB];     // cell-sorted interleaved (pack, orig idx)
__device__ uint2 g_acand[B_][NA];     // supercell-sorted interleaved (pack, orig row)

// ---------------------------------------------------------------------------
// Binning: grid (B_, 2). y=0: b-points into 512 cells; y=1: a-points into 64
// supercells. SMEM-atomic histogram, warp-shuffle scans, SMEM-cursor scatter.
// ---------------------------------------------------------------------------
__global__ __launch_bounds__(TB) void k_bin(
    const int* __restrict__ ac, const int* __restrict__ bc)
{
    const int b = blockIdx.x, t = threadIdx.x, lane = t & 31, wid = t >> 5;

    if (blockIdx.y == 0) {
        // ---- b role: 512 cells ----
        __shared__ int h[NCELL];
        __shared__ int wsum[16];
        h[t] = 0;
        __syncthreads();

        uint32_t pk[8]; int cl[8];
        const int* base = bc + (size_t)b * NB * 3;
        #pragma unroll
        for (int i = 0; i < 8; i++) {
            const int m = t + i * TB;
            const int* c = base + (size_t)m * 3;
            uint32_t x = ((uint32_t)c[0]) >> 4, y = ((uint32_t)c[1]) >> 4, z = ((uint32_t)c[2]) >> 4;
            pk[i] = x | (y << 8) | (z << 16);
            cl[i] = (int)(x >> 4) + GC * (int)(y >> 4) + GC * GC * (int)(z >> 4);
            atomicAdd(&h[cl[i]], 1);
        }
        __syncthreads();

        const int v = h[t];
        int incl = v;
        #pragma unroll
        for (int d = 1; d < 32; d <<= 1) {
            int u = __shfl_up_sync(~0u, incl, d);
            if (lane >= d) incl += u;
        }
        if (lane == 31) wsum[wid] = incl;
        __syncthreads();
        if (wid == 0) {
            int s = (lane < 16) ? wsum[lane] : 0;
            #pragma unroll
            for (int d = 1; d < 16; d <<= 1) {
                int u = __shfl_up_sync(~0u, s, d);
                if (lane >= d) s += u;
            }
            if (lane < 16) wsum[lane] = s;
        }
        __syncthreads();
        const int inclT = incl + (wid > 0 ? wsum[wid - 1] : 0);
        g_bstart[b][t + 1] = inclT;
        if (t == 0) g_bstart[b][0] = 0;
        h[t] = inclT - v;          // exclusive -> cursor
        __syncthreads();

        uint2* bo = g_bcand[b];
        #pragma unroll
        for (int i = 0; i < 8; i++) {
            const int m = t + i * TB;
            const int pos = atomicAdd(&h[cl[i]], 1);
            bo[pos] = make_uint2(pk[i], (uint32_t)m);
        }
    } else {
        // ---- a role: 64 supercells ----
        __shared__ int h[NSC];
        __shared__ int wsum[2];
        if (t < NSC) h[t] = 0;
        __syncthreads();

        uint32_t pk[8]; int cl[8];
        const int* base = ac + (size_t)b * NA * 3;
        #pragma unroll
        for (int i = 0; i < 8; i++) {
            const int m = t + i * TB;
            const int* c = base + (size_t)m * 3;
            uint32_t x = ((uint32_t)c[0]) >> 4, y = ((uint32_t)c[1]) >> 4, z = ((uint32_t)c[2]) >> 4;
            pk[i] = x | (y << 8) | (z << 16);
            cl[i] = (int)(x >> 5) + 4 * (int)(y >> 5) + 16 * (int)(z >> 5);
            atomicAdd(&h[cl[i]], 1);
        }
        __syncthreads();

        int v = 0, incl = 0;
        if (t < NSC) {
            v = h[t];
            incl = v;
            #pragma unroll
            for (int d = 1; d < 32; d <<= 1) {
                int u = __shfl_up_sync(~0u, incl, d);
                if (lane >= d) incl += u;
            }
            if (lane == 31) wsum[wid] = incl;
        }
        __syncthreads();
        if (t < NSC) {
            const int inclT = incl + (wid == 1 ? wsum[0] : 0);
            g_astart[b][t + 1] = inclT;
            if (t == 0) g_astart[b][0] = 0;
            h[t] = inclT - v;
        }
        __syncthreads();

        uint2* ao = g_acand[b];
        #pragma unroll
        for (int i = 0; i < 8; i++) {
            const int m = t + i * TB;
            const int pos = atomicAdd(&h[cl[i]], 1);
            ao[pos] = make_uint2(pk[i], (uint32_t)m);
        }
    }
}

__device__ __forceinline__ void insert3(uint32_t key, uint32_t& b0, uint32_t& b1, uint32_t& b2) {
    uint32_t t1 = min(b1, max(b0, key));
    uint32_t t2 = min(b2, max(b1, key));
    b0 = min(b0, key);
    b1 = t1;
    b2 = t2;
}

// ---------------------------------------------------------------------------
// Main: grid (NSC, B_, ZS), block 256 (8 warps). Each warp directly scans 2 of
// the <=16 candidate cell-runs from global (uniform LDG.64, L2-resident); one
// barrier to merge partials, one before the block-parallel epilogue.
// ---------------------------------------------------------------------------
__global__ __launch_bounds__(TM) void k_main(
    const float* __restrict__ a_feats, const float* __restrict__ b_feats,
    float* __restrict__ out)
{
    __shared__ uint4  sm_top[8][32];   // per-warp top-3 partials (+pad)
    __shared__ int4   sm_ri[32];       // {i0,i1,i2,orow}
    __shared__ float4 sm_rw[32];       // {w0,w1,w2,pad}

    const int b = blockIdx.y, scid = blockIdx.x;
    const int tid = threadIdx.x, lane = tid & 31, w = tid >> 5;

    const int astart = g_astart[b][scid], aend = g_astart[b][scid + 1];
    const int abase0 = astart + (int)blockIdx.z * 32;
    if (abase0 >= aend) return;

    // Candidate region: 4x4x4 cells around the supercell (clipped)
    const int sx = scid & 3, sy = (scid >> 2) & 3, sz = scid >> 4;
    const int x0 = max(0, 2 * sx - 1), x1 = min(GC - 1, 2 * sx + 2);
    const int y0 = max(0, 2 * sy - 1), y1 = min(GC - 1, 2 * sy + 2);
    const int z0 = max(0, 2 * sz - 1), z1 = min(GC - 1, 2 * sz + 2);
    const int ny = y1 - y0 + 1, nz = z1 - z0 + 1, nrun = ny * nz;
    const int xlen = x1 - x0 + 1;

    // This warp's (up to) 2 runs — warp-uniform bounds
    int s0 = 0, e0 = 0, s1 = 0, e1 = 0;
    {
        const int r0 = 2 * w, r1 = 2 * w + 1;
        if (r0 < nrun) {
            const int cy = y0 + r0 % ny, cz = z0 + r0 / ny;
            const int c0 = x0 + GC * cy + GC * GC * cz;
            s0 = g_bstart[b][c0];
            e0 = g_bstart[b][c0 + xlen];
        }
        if (r1 < nrun) {
            const int cy = y0 + r1 % ny, cz = z0 + r1 / ny;
            const int c0 = x0 + GC * cy + GC * GC * cz;
            s1 = g_bstart[b][c0];
            e1 = g_bstart[b][c0 + xlen];
        }
    }

    const uint2* __restrict__ bcand = g_bcand[b];
    const uint2* __restrict__ acand = g_acand[b];
    const float* bf = b_feats + (size_t)b * NB * D_;

    for (int abase = abase0; abase < aend; abase += ZS * 32) {
        const int ap = abase + lane;
        const bool valid = ap < aend;
        const uint2 av = valid ? acand[ap] : make_uint2(0u, 0u);
        const uint32_t pa = av.x;

        // Dual accumulator chains
        uint32_t a0 = ~0u, a1 = ~0u, a2 = ~0u;
        uint32_t c0 = ~0u, c1 = ~0u, c2 = ~0u;

        #pragma unroll 1
        for (int run = 0; run < 2; run++) {
            const int s = run ? s1 : s0, e = run ? e1 : e0;
            int i = s;
            for (; i + 1 < e; i += 2) {
                const uint2 cda = bcand[i];       // uniform LDG.64 broadcast
                const uint2 cdb = bcand[i + 1];
                uint32_t v, d2;
                v = __vabsdiffu4(pa, cda.x); d2 = __dp4a(v, v, 0u);
                insert3(d2 * 4096u + cda.y, a0, a1, a2);
                v = __vabsdiffu4(pa, cdb.x); d2 = __dp4a(v, v, 0u);
                insert3(d2 * 4096u + cdb.y, c0, c1, c2);
            }
            if (i < e) {
                const uint2 cda = bcand[i];
                uint32_t v = __vabsdiffu4(pa, cda.x);
                uint32_t d2 = __dp4a(v, v, 0u);
                insert3(d2 * 4096u + cda.y, a0, a1, a2);
            }
        }
        insert3(c0, a0, a1, a2);
        insert3(c1, a0, a1, a2);
        insert3(c2, a0, a1, a2);

        sm_top[w][lane] = make_uint4(a0, a1, a2, 0u);
        __syncthreads();

        if (w == 0) {
            #pragma unroll
            for (int ss = 1; ss < 8; ss++) {
                const uint4 t = sm_top[ss][lane];    // LDS.128
                insert3(t.x, a0, a1, a2);
                insert3(t.y, a0, a1, a2);
                insert3(t.z, a0, a1, a2);
            }

            // Exactness: region covers ball(a,16). If 3rd-best d2 >= 256,
            // exact full scan for this lane (astronomically rare).
            if (valid && (a2 >> 12) >= 256u) {
                a0 = a1 = a2 = ~0u;
                for (int m = 0; m < NB; m++) {
                    const uint2 cd = bcand[m];
                    const uint32_t vv = __vabsdiffu4(pa, cd.x);
                    const uint32_t d2 = __dp4a(vv, vv, 0u);
                    insert3(d2 * 4096u + cd.y, a0, a1, a2);
                }
            }

            const uint32_t keys[3] = { a0, a1, a2 };
            int   ii[3]; float ww[3];
            #pragma unroll
            for (int k = 0; k < 3; k++) {
                const uint32_t d2 = keys[k] >> 12;
                ii[k] = (int)(keys[k] & 0xFFFu);
                const float dist = sqrtf((float)d2) * (1.0f / 128.0f);
                ww[k] = fmaxf(0.5f - dist, 0.0f);
            }
            sm_ri[lane] = make_int4(ii[0], ii[1], ii[2], (int)av.y);
            sm_rw[lane] = make_float4(ww[0], ww[1], ww[2], 0.0f);
        }
        __syncthreads();

        // Block-parallel epilogue: nval rows x 32 float4 columns, MLP ~4/thread
        const int nval = min(32, aend - abase);
        for (int u = tid; u < nval * 32; u += TM) {
            const int r = u >> 5, c4 = u & 31;
            const int4   ri = sm_ri[r];
            const float4 rw = sm_rw[r];
            const int orow = ri.w;
            float4 val;
            if (c4 < 16) {
                val = ((const float4*)(a_feats + ((size_t)b * NA + orow) * D_))[c4];
            } else {
                const int cc = c4 - 16;
                const float4 f0 = ((const float4*)(bf + (size_t)ri.x * D_))[cc];
                const float4 f1 = ((const float4*)(bf + (size_t)ri.y * D_))[cc];
                const float4 f2 = ((const float4*)(bf + (size_t)ri.z * D_))[cc];
                val.x = rw.x * f0.x + rw.y * f1.x + rw.z * f2.x;
                val.y = rw.x * f0.y + rw.y * f1.y + rw.z * f2.y;
                val.z = rw.x * f0.z + rw.y * f1.z + rw.z * f2.z;
                val.w = rw.x * f0.w + rw.y * f1.w + rw.z * f2.w;
            }
            ((float4*)(out + ((size_t)b * NA + orow) * 2 * D_))[c4] = val;
        }
        __syncthreads();  // protect sm_* before next a-set
    }
}

extern "C" void kernel_launch(void* const* d_in, const int* in_sizes, int n_in,
                              void* d_out, int out_size)
{
    const float* a_feats  = (const float*)d_in[0];
    const float* b_feats  = (const float*)d_in[1];
    const int*   a_coords = (const int*)d_in[2];
    const int*   b_coords = (const int*)d_in[3];
    float*       out      = (float*)d_out;

    dim3 gbin(B_, 2);
    k_bin<<<gbin, TB>>>(a_coords, b_coords);
    dim3 grid(NSC, B_, ZS);
    k_main<<<grid, TM>>>(a_feats, b_feats, out);
}

// round 14
// speedup vs baseline: 1.5102x; 1.0778x over previous
#include <cuda_runtime.h>
#include <cstdint>

// Shapes fixed for this benchmark
constexpr int B_ = 8, NA = 4096, NB = 4096, D_ = 64;
constexpr int GC = 8;                 // 16-wide cells per axis -> 8^3 = 512 cells
constexpr int NCELL = GC * GC * GC;   // 512
constexpr int NSC = 64;               // 32-wide supercells -> 4^3
constexpr int TM = 256;               // k_main threads (8 warps)
constexpr int TB = 512;               // k_bin threads
constexpr int ZS = 4;                 // a-set splits per supercell

// Scratch (device globals: no allocation allowed)
__device__ int   g_bstart[B_][NCELL + 1];
__device__ int   g_astart[B_][NSC + 1];
__device__ uint2 g_bcand[B_][NB];     // cell-sorted interleaved (pack, orig idx)
__device__ uint2 g_acand[B_][NA];     // supercell-sorted interleaved (pack, orig row)

// ---------------------------------------------------------------------------
// Binning: grid (B_, 2). y=0: b-points into 512 cells; y=1: a-points into 64
// supercells. SMEM-atomic histogram, warp-shuffle scans, SMEM-cursor scatter.
// ---------------------------------------------------------------------------
__global__ __launch_bounds__(TB) void k_bin(
    const int* __restrict__ ac, const int* __restrict__ bc)
{
    const int b = blockIdx.x, t = threadIdx.x, lane = t & 31, wid = t >> 5;

    if (blockIdx.y == 0) {
        // ---- b role: 512 cells ----
        __shared__ int h[NCELL];
        __shared__ int wsum[16];
        h[t] = 0;
        __syncthreads();

        uint32_t pk[8]; int cl[8];
        const int* base = bc + (size_t)b * NB * 3;
        #pragma unroll
        for (int i = 0; i < 8; i++) {
            const int m = t + i * TB;
            const int* c = base + (size_t)m * 3;
            uint32_t x = ((uint32_t)c[0]) >> 4, y = ((uint32_t)c[1]) >> 4, z = ((uint32_t)c[2]) >> 4;
            pk[i] = x | (y << 8) | (z << 16);
            cl[i] = (int)(x >> 4) + GC * (int)(y >> 4) + GC * GC * (int)(z >> 4);
            atomicAdd(&h[cl[i]], 1);
        }
        __syncthreads();

        const int v = h[t];
        int incl = v;
        #pragma unroll
        for (int d = 1; d < 32; d <<= 1) {
            int u = __shfl_up_sync(~0u, incl, d);
            if (lane >= d) incl += u;
        }
        if (lane == 31) wsum[wid] = incl;
        __syncthreads();
        if (wid == 0) {
            int s = (lane < 16) ? wsum[lane] : 0;
            #pragma unroll
            for (int d = 1; d < 16; d <<= 1) {
                int u = __shfl_up_sync(~0u, s, d);
                if (lane >= d) s += u;
            }
            if (lane < 16) wsum[lane] = s;
        }
        __syncthreads();
        const int inclT = incl + (wid > 0 ? wsum[wid - 1] : 0);
        g_bstart[b][t + 1] = inclT;
        if (t == 0) g_bstart[b][0] = 0;
        h[t] = inclT - v;          // exclusive -> cursor
        __syncthreads();

        uint2* bo = g_bcand[b];
        #pragma unroll
        for (int i = 0; i < 8; i++) {
            const int m = t + i * TB;
            const int pos = atomicAdd(&h[cl[i]], 1);
            bo[pos] = make_uint2(pk[i], (uint32_t)m);
        }
    } else {
        // ---- a role: 64 supercells ----
        __shared__ int h[NSC];
        __shared__ int wsum[2];
        if (t < NSC) h[t] = 0;
        __syncthreads();

        uint32_t pk[8]; int cl[8];
        const int* base = ac + (size_t)b * NA * 3;
        #pragma unroll
        for (int i = 0; i < 8; i++) {
            const int m = t + i * TB;
            const int* c = base + (size_t)m * 3;
            uint32_t x = ((uint32_t)c[0]) >> 4, y = ((uint32_t)c[1]) >> 4, z = ((uint32_t)c[2]) >> 4;
            pk[i] = x | (y << 8) | (z << 16);
            cl[i] = (int)(x >> 5) + 4 * (int)(y >> 5) + 16 * (int)(z >> 5);
            atomicAdd(&h[cl[i]], 1);
        }
        __syncthreads();

        int v = 0, incl = 0;
        if (t < NSC) {
            v = h[t];
            incl = v;
            #pragma unroll
            for (int d = 1; d < 32; d <<= 1) {
                int u = __shfl_up_sync(~0u, incl, d);
                if (lane >= d) incl += u;
            }
            if (lane == 31) wsum[wid] = incl;
        }
        __syncthreads();
        if (t < NSC) {
            const int inclT = incl + (wid == 1 ? wsum[0] : 0);
            g_astart[b][t + 1] = inclT;
            if (t == 0) g_astart[b][0] = 0;
            h[t] = inclT - v;
        }
        __syncthreads();

        uint2* ao = g_acand[b];
        #pragma unroll
        for (int i = 0; i < 8; i++) {
            const int m = t + i * TB;
            const int pos = atomicAdd(&h[cl[i]], 1);
            ao[pos] = make_uint2(pk[i], (uint32_t)m);
        }
    }
}

__device__ __forceinline__ void insert3(uint32_t key, uint32_t& b0, uint32_t& b1, uint32_t& b2) {
    uint32_t t1 = min(b1, max(b0, key));
    uint32_t t2 = min(b2, max(b1, key));
    b0 = min(b0, key);
    b1 = t1;
    b2 = t2;
}

__device__ __forceinline__ void eval1(uint32_t pa, uint32_t pk, uint32_t idx,
                                      uint32_t& b0, uint32_t& b1, uint32_t& b2) {
    const uint32_t v  = __vabsdiffu4(pa, pk);
    const uint32_t d2 = __dp4a(v, v, 0u);
    insert3(d2 * 4096u + idx, b0, b1, b2);
}

// ---------------------------------------------------------------------------
// Main: grid (NSC, B_, ZS), block 256 (8 warps). Each warp directly scans 2 of
// the <=16 candidate cell-runs from global; candidates are consumed in batches
// of 8 via four uniform LDG.128 (MLP=4). Key set is order-independent (unique
// keys), so peel/batch reordering is exact.
// ---------------------------------------------------------------------------
__global__ __launch_bounds__(TM) void k_main(
    const float* __restrict__ a_feats, const float* __restrict__ b_feats,
    float* __restrict__ out)
{
    __shared__ uint4  sm_top[8][32];   // per-warp top-3 partials (+pad)
    __shared__ int4   sm_ri[32];       // {i0,i1,i2,orow}
    __shared__ float4 sm_rw[32];       // {w0,w1,w2,pad}

    const int b = blockIdx.y, scid = blockIdx.x;
    const int tid = threadIdx.x, lane = tid & 31, w = tid >> 5;

    const int astart = g_astart[b][scid], aend = g_astart[b][scid + 1];
    const int abase0 = astart + (int)blockIdx.z * 32;
    if (abase0 >= aend) return;

    // Candidate region: 4x4x4 cells around the supercell (clipped)
    const int sx = scid & 3, sy = (scid >> 2) & 3, sz = scid >> 4;
    const int x0 = max(0, 2 * sx - 1), x1 = min(GC - 1, 2 * sx + 2);
    const int y0 = max(0, 2 * sy - 1), y1 = min(GC - 1, 2 * sy + 2);
    const int z0 = max(0, 2 * sz - 1), z1 = min(GC - 1, 2 * sz + 2);
    const int ny = y1 - y0 + 1, nz = z1 - z0 + 1, nrun = ny * nz;
    const int xlen = x1 - x0 + 1;

    // This warp's (up to) 2 runs — warp-uniform bounds
    int s0 = 0, e0 = 0, s1 = 0, e1 = 0;
    {
        const int r0 = 2 * w, r1 = 2 * w + 1;
        if (r0 < nrun) {
            const int cy = y0 + r0 % ny, cz = z0 + r0 / ny;
            const int c0 = x0 + GC * cy + GC * GC * cz;
            s0 = g_bstart[b][c0];
            e0 = g_bstart[b][c0 + xlen];
        }
        if (r1 < nrun) {
            const int cy = y0 + r1 % ny, cz = z0 + r1 / ny;
            const int c0 = x0 + GC * cy + GC * GC * cz;
            s1 = g_bstart[b][c0];
            e1 = g_bstart[b][c0 + xlen];
        }
    }

    const uint2* __restrict__ bcand = g_bcand[b];
    const uint2* __restrict__ acand = g_acand[b];
    const float* bf = b_feats + (size_t)b * NB * D_;

    for (int abase = abase0; abase < aend; abase += ZS * 32) {
        const int ap = abase + lane;
        const bool valid = ap < aend;
        const uint2 av = valid ? acand[ap] : make_uint2(0u, 0u);
        const uint32_t pa = av.x;

        // Dual accumulator chains
        uint32_t a0 = ~0u, a1 = ~0u, a2 = ~0u;
        uint32_t c0 = ~0u, c1 = ~0u, c2 = ~0u;

        #pragma unroll 1
        for (int run = 0; run < 2; run++) {
            const int s = run ? s1 : s0, e = run ? e1 : e0;
            int i = s;
            // Peel to 16B alignment (uint2 array: even index = 16B aligned)
            if (i < e && (i & 1)) {
                const uint2 cd = bcand[i];
                eval1(pa, cd.x, cd.y, a0, a1, a2);
                i++;
            }
            // Batches of 8 candidates: 4 uniform LDG.128 in flight
            for (; i + 8 <= e; i += 8) {
                const uint4 p0 = *(const uint4*)(bcand + i);
                const uint4 p1 = *(const uint4*)(bcand + i + 2);
                const uint4 p2 = *(const uint4*)(bcand + i + 4);
                const uint4 p3 = *(const uint4*)(bcand + i + 6);
                eval1(pa, p0.x, p0.y, a0, a1, a2);
                eval1(pa, p0.z, p0.w, c0, c1, c2);
                eval1(pa, p1.x, p1.y, a0, a1, a2);
                eval1(pa, p1.z, p1.w, c0, c1, c2);
                eval1(pa, p2.x, p2.y, a0, a1, a2);
                eval1(pa, p2.z, p2.w, c0, c1, c2);
                eval1(pa, p3.x, p3.y, a0, a1, a2);
                eval1(pa, p3.z, p3.w, c0, c1, c2);
            }
            // Remainder (<8)
            for (; i + 2 <= e; i += 2) {
                const uint4 p0 = *(const uint4*)(bcand + i);
                eval1(pa, p0.x, p0.y, a0, a1, a2);
                eval1(pa, p0.z, p0.w, c0, c1, c2);
            }
            if (i < e) {
                const uint2 cd = bcand[i];
                eval1(pa, cd.x, cd.y, a0, a1, a2);
            }
        }
        insert3(c0, a0, a1, a2);
        insert3(c1, a0, a1, a2);
        insert3(c2, a0, a1, a2);

        sm_top[w][lane] = make_uint4(a0, a1, a2, 0u);
        __syncthreads();

        if (w == 0) {
            #pragma unroll
            for (int ss = 1; ss < 8; ss++) {
                const uint4 t = sm_top[ss][lane];    // LDS.128
                insert3(t.x, a0, a1, a2);
                insert3(t.y, a0, a1, a2);
                insert3(t.z, a0, a1, a2);
            }

            // Exactness: region covers ball(a,16). If 3rd-best d2 >= 256,
            // exact full scan for this lane (astronomically rare).
            if (valid && (a2 >> 12) >= 256u) {
                a0 = a1 = a2 = ~0u;
                for (int m = 0; m < NB; m++) {
                    const uint2 cd = bcand[m];
                    eval1(pa, cd.x, cd.y, a0, a1, a2);
                }
            }

            const uint32_t keys[3] = { a0, a1, a2 };
            int   ii[3]; float ww[3];
            #pragma unroll
            for (int k = 0; k < 3; k++) {
                const uint32_t d2 = keys[k] >> 12;
                ii[k] = (int)(keys[k] & 0xFFFu);
                const float dist = sqrtf((float)d2) * (1.0f / 128.0f);
                ww[k] = fmaxf(0.5f - dist, 0.0f);
            }
            sm_ri[lane] = make_int4(ii[0], ii[1], ii[2], (int)av.y);
            sm_rw[lane] = make_float4(ww[0], ww[1], ww[2], 0.0f);
        }
        __syncthreads();

        // Block-parallel epilogue: nval rows x 32 float4 columns, MLP ~4/thread
        const int nval = min(32, aend - abase);
        for (int u = tid; u < nval * 32; u += TM) {
            const int r = u >> 5, c4 = u & 31;
            const int4   ri = sm_ri[r];
            const float4 rw = sm_rw[r];
            const int orow = ri.w;
            float4 val;
            if (c4 < 16) {
                val = ((const float4*)(a_feats + ((size_t)b * NA + orow) * D_))[c4];
            } else {
                const int cc = c4 - 16;
                const float4 f0 = ((const float4*)(bf + (size_t)ri.x * D_))[cc];
                const float4 f1 = ((const float4*)(bf + (size_t)ri.y * D_))[cc];
                const float4 f2 = ((const float4*)(bf + (size_t)ri.z * D_))[cc];
                val.x = rw.x * f0.x + rw.y * f1.x + rw.z * f2.x;
                val.y = rw.x * f0.y + rw.y * f1.y + rw.z * f2.y;
                val.z = rw.x * f0.z + rw.y * f1.z + rw.z * f2.z;
                val.w = rw.x * f0.w + rw.y * f1.w + rw.z * f2.w;
            }
            ((float4*)(out + ((size_t)b * NA + orow) * 2 * D_))[c4] = val;
        }
        __syncthreads();  // protect sm_* before next a-set
    }
}

extern "C" void kernel_launch(void* const* d_in, const int* in_sizes, int n_in,
                              void* d_out, int out_size)
{
    const float* a_feats  = (const float*)d_in[0];
    const float* b_feats  = (const float*)d_in[1];
    const int*   a_coords = (const int*)d_in[2];
    const int*   b_coords = (const int*)d_in[3];
    float*       out      = (float*)d_out;

    dim3 gbin(B_, 2);
    k_bin<<<gbin, TB>>>(a_coords, b_coords);
    dim3 grid(NSC, B_, ZS);
    k_main<<<grid, TM>>>(a_feats, b_feats, out);
}